// round 14
// baseline (speedup 1.0000x reference)
#include <cuda_runtime.h>
#include <math.h>

typedef unsigned long long u64;

__device__ __forceinline__ void fma2(u64& acc, u64 a2, u64 b2) {
    asm("fma.rn.f32x2 %0, %1, %2, %0;" : "+l"(acc) : "l"(a2), "l"(b2));
}
__device__ __forceinline__ u64 splat2(float v) {
    u64 a2;
    asm("mov.b64 %0, {%1, %1};" : "=l"(a2) : "r"(__float_as_uint(v)));
    return a2;
}
__device__ __forceinline__ void unpack2(u64 p, float& lo, float& hi) {
    unsigned l, h;
    asm("mov.b64 {%0, %1}, %2;" : "=r"(l), "=r"(h) : "l"(p));
    lo = __uint_as_float(l); hi = __uint_as_float(h);
}

#define BAR_ALL()  asm volatile("bar.sync 0, 160;" ::: "memory")
#define BAR_DATA() asm volatile("bar.sync 1, 128;" ::: "memory")

// ---------------------------------------------------------------------------
// Single fused kernel. One block per batch row, 160 threads:
//   threads 0-127 (warps 0-3): data path (t = tid).
//   threads 128-159 (warp 4): redundant per-block eigen solve for c.
// Math (verified through R12, rel_err ~1e-6):
//   L = normalized lap (block-tridiag: Mi/Mb diag blocks + diagonal edges).
//   c = 2/sigma_max(L); sigma_max exact via modal decomposition: max over
//   temporal modes is at lam = +/-2cos(pi/129) (convexity of norm in lam);
//   per mode: 16-step Lanczos on B = A^T A (exact in 16 dims) + Sturm.
//   out = bias + x*G0 + c*(u1*P1) + c^2*(u2*P2), u1 = L^T x, u2 = L^T u1,
//   G0 = W0-W1+W2, P1 = W1-4W2, P2 = 2W2.  c only enters the epilogue, so
//   the eigen warp's latency chain overlaps the whole data path.
// ---------------------------------------------------------------------------
__global__ void __launch_bounds__(160) sgconv_fused_kernel(
    const float* __restrict__ x, const float* __restrict__ weight,
    const float* __restrict__ bias, const float* __restrict__ adj,
    float* __restrict__ out)
{
    __shared__ __align__(16) float sAhat[16][16];
    __shared__ __align__(16) float sMi[16][16], sMb[16][16];   // M[g][r]
    __shared__ __align__(16) float sA[2][16][16], sB[2][16][16];
    __shared__ __align__(16) float spb[16], spi[16];
    __shared__ __align__(16) float se_i[16], se_b[16];
    __shared__ __align__(16) float sG0[16][16], sP1[16][16], sP2[16][16];
    __shared__ __align__(16) float sb16[16];
    __shared__ float sc;
    __shared__ __align__(16) float xsh[128][20];
    __shared__ __align__(16) float ush[128][20];

    const int tid = threadIdx.x;
    const int t = tid;                 // time step (data threads)
    const bool isData = (tid < 128);

    // kick off x global load early
    float4 xv0, xv1, xv2, xv3;
    if (isData) {
        const float4* xb = (const float4*)(x + (size_t)blockIdx.x * 2048 + t * 16);
        xv0 = xb[0]; xv1 = xb[1]; xv2 = xb[2]; xv3 = xb[3];
    }

    // ---- prologue: Ahat + weight combos + bias ----
    for (int i = tid; i < 256; i += 160) {
        int f = i >> 4, g = i & 15;
        sAhat[f][g] = (f == g) ? 1.0f : 1.0f / (1.0f + expf(-adj[i]));
        float w0 = weight[i], w1 = weight[256 + i], w2 = weight[512 + i];
        sG0[f][g] = w0 - w1 + w2;
        sP1[f][g] = w1 - 4.0f * w2;
        sP2[f][g] = 2.0f * w2;
    }
    if (tid < 16) sb16[tid] = bias[tid];
    BAR_ALL();   // #1

    if (tid < 16) {
        float a = 0.0f;
        #pragma unroll
        for (int g = 0; g < 16; g++) a += sAhat[tid][g];   // includes diag 1
        spb[tid] = rsqrtf(a + 1.0f);
        spi[tid] = rsqrtf(a + 2.0f);
    }
    BAR_ALL();   // #2

    for (int i = tid; i < 256; i += 160) {
        int f = i >> 4, g = i & 15;
        float diag = (f == g) ? 1.0f : 0.0f;
        sMi[f][g] = diag - spi[f] * sAhat[f][g] * spi[g];
        sMb[f][g] = diag - spb[f] * sAhat[f][g] * spb[g];
    }
    if (tid < 16) {
        se_i[tid] = -spi[tid] * spi[tid];
        se_b[tid] = -spb[tid] * spi[tid];
    }
    if (isData) {   // publish x tile
        float4* dst = (float4*)&xsh[t][0];
        dst[0] = xv0; dst[1] = xv1; dst[2] = xv2; dst[3] = xv3;
    }
    BAR_ALL();   // #3

    for (int i = tid; i < 512; i += 160) {   // A_h = Mi + lam_h diag(eii)
        int h = i >> 8, idx = i & 255;
        int k = idx >> 4, ii = idx & 15;
        float lam = (h ? -2.0f : 2.0f) * cosf(3.14159265358979f / 129.0f);
        sA[h][k][ii] = sMi[k][ii] + ((k == ii) ? lam * se_i[k] : 0.0f);
    }
    BAR_ALL();   // #4

    for (int i = tid; i < 512; i += 160) {   // B_h = A_h^T A_h
        int h = i >> 8, idx = i & 255;
        int ii = idx >> 4, j = idx & 15;
        float acc = 0.0f;
        #pragma unroll
        for (int k = 0; k < 16; k++) acc += sA[h][k][ii] * sA[h][k][j];
        sB[h][ii][j] = acc;
    }
    BAR_ALL();   // #5

    if (!isData) {
        // ===== eigen warp: Lanczos(16, exact) + grid Sturm -> c =====
        const int lane = tid - 128;
        const int half = lane >> 4;
        const int f    = lane & 15;
        const int base = half << 4;

        float Mr[16];
        #pragma unroll
        for (int g = 0; g < 16; g++) Mr[g] = sB[half][f][g];

        float v, vp = 0.0f;
        {
            unsigned h = (unsigned)(f * 2654435761u) + 0x9E3779B9u;
            h ^= h >> 15; h *= 0x2C1B3C6Du; h ^= h >> 12; h *= 0x297A2D39u; h ^= h >> 15;
            v = (float)(h & 0xFFFFFFu) * (1.0f / 16777216.0f) - 0.5f + 0.03f * (float)f;
            float nn = v * v;
            #pragma unroll
            for (int o = 8; o > 0; o >>= 1) nn += __shfl_xor_sync(0xFFFFFFFFu, nn, o);
            v *= rsqrtf(nn);
        }

        float al[16], be[16];
        float bprev = 0.0f;
        #pragma unroll
        for (int it = 0; it < 16; it++) {
            float w = 0.0f;
            #pragma unroll
            for (int g = 0; g < 16; g++)
                w += Mr[g] * __shfl_sync(0xFFFFFFFFu, v, base + g);
            float pa = v * w;
            #pragma unroll
            for (int o = 8; o > 0; o >>= 1) pa += __shfl_xor_sync(0xFFFFFFFFu, pa, o);
            float alpha = pa;
            w -= alpha * v + bprev * vp;
            float ps = w * w;
            #pragma unroll
            for (int o = 8; o > 0; o >>= 1) ps += __shfl_xor_sync(0xFFFFFFFFu, ps, o);
            float beta = sqrtf(ps);
            al[it] = alpha; be[it] = beta;
            float rb = (beta > 1e-30f) ? 1.0f / beta : 0.0f;
            vp = v; v = w * rb;
            bprev = beta;
        }

        float lo = 0.0f, hi = 8.0f;
        for (int r = 0; r < 6; r++) {
            float xg = lo + (hi - lo) * (float)(f + 1) * (1.0f / 17.0f);
            int cnt = 0;
            float d = al[0] - xg;
            if (d < 0.0f) cnt++;
            #pragma unroll
            for (int i = 1; i < 16; i++) {
                float dd = (fabsf(d) < 1e-25f) ? ((d < 0.0f) ? -1e-25f : 1e-25f) : d;
                d = (al[i] - xg) - (be[i - 1] * be[i - 1]) / dd;
                if (d < 0.0f) cnt++;
            }
            bool ge = (cnt < 16);
            unsigned m = (__ballot_sync(0xFFFFFFFFu, ge) >> (half << 4)) & 0xFFFFu;
            int nge = __popc(m);
            float w17 = (hi - lo) * (1.0f / 17.0f);
            lo = lo + w17 * (float)nge;
            hi = lo + w17;
        }
        float lmax = 0.5f * (lo + hi);
        float other = __shfl_sync(0xFFFFFFFFu, lmax, lane ^ 16);
        lmax = fmaxf(lmax, other);
        if (lane == 0) sc = 2.0f / sqrtf(lmax);

        BAR_ALL();   // #6 join
        return;
    }

    // ===== data path (tid < 128) =====
    const bool bnd = (t == 0 || t == 127);
    const float (*Mp)[16] = bnd ? sMb : sMi;

    float xw[16] = { xv0.x, xv0.y, xv0.z, xv0.w,  xv1.x, xv1.y, xv1.z, xv1.w,
                     xv2.x, xv2.y, xv2.z, xv2.w,  xv3.x, xv3.y, xv3.z, xv3.w };

    // edge-term helper (packed, elementwise)
    auto add_edges = [&](const float (&nbr)[128][20], u64 (&dst)[8]) {
        if (t > 0) {
            const float* el = (t == 1 || t == 127) ? se_b : se_i;
            const ulonglong2* e2 = (const ulonglong2*)el;
            const ulonglong2* nm = (const ulonglong2*)&nbr[t - 1][0];
            #pragma unroll
            for (int q = 0; q < 4; q++) {
                ulonglong2 ee = e2[q], nn = nm[q];
                fma2(dst[2*q],   ee.x, nn.x);
                fma2(dst[2*q+1], ee.y, nn.y);
            }
        }
        if (t < 127) {
            const float* er = (t == 0 || t == 126) ? se_b : se_i;
            const ulonglong2* e2 = (const ulonglong2*)er;
            const ulonglong2* np = (const ulonglong2*)&nbr[t + 1][0];
            #pragma unroll
            for (int q = 0; q < 4; q++) {
                ulonglong2 ee = e2[q], nn = np[q];
                fma2(dst[2*q],   ee.x, nn.x);
                fma2(dst[2*q+1], ee.y, nn.y);
            }
        }
    };

    // acc0 = bias
    u64 acc0[8];
    {
        const ulonglong2* b2 = (const ulonglong2*)sb16;
        ulonglong2 b01 = b2[0], b23 = b2[1], b45 = b2[2], b67 = b2[3];
        acc0[0] = b01.x; acc0[1] = b01.y; acc0[2] = b23.x; acc0[3] = b23.y;
        acc0[4] = b45.x; acc0[5] = b45.y; acc0[6] = b67.x; acc0[7] = b67.y;
    }

    // u1 = L^T x  (combined with acc0 += x*G0, sharing splats)
    u64 u12[8];
    #pragma unroll
    for (int q = 0; q < 8; q++) u12[q] = 0ull;
    add_edges(xsh, u12);
    #pragma unroll
    for (int g = 0; g < 16; g++) {
        u64 a2 = splat2(xw[g]);
        const ulonglong2* mr = (const ulonglong2*)&Mp[g][0];
        const ulonglong2* g0 = (const ulonglong2*)&sG0[g][0];
        ulonglong2 mA = mr[0], mB = mr[1], mC = mr[2], mD = mr[3];
        ulonglong2 hA = g0[0], hB = g0[1], hC = g0[2], hD = g0[3];
        fma2(u12[0], a2, mA.x); fma2(u12[1], a2, mA.y);
        fma2(u12[2], a2, mB.x); fma2(u12[3], a2, mB.y);
        fma2(u12[4], a2, mC.x); fma2(u12[5], a2, mC.y);
        fma2(u12[6], a2, mD.x); fma2(u12[7], a2, mD.y);
        fma2(acc0[0], a2, hA.x); fma2(acc0[1], a2, hA.y);
        fma2(acc0[2], a2, hB.x); fma2(acc0[3], a2, hB.y);
        fma2(acc0[4], a2, hC.x); fma2(acc0[5], a2, hC.y);
        fma2(acc0[6], a2, hD.x); fma2(acc0[7], a2, hD.y);
    }
    {   // publish u1
        ulonglong2* up = (ulonglong2*)&ush[t][0];
        ulonglong2 a, b;
        a.x = u12[0]; a.y = u12[1]; b.x = u12[2]; b.y = u12[3];
        up[0] = a; up[1] = b;
        a.x = u12[4]; a.y = u12[5]; b.x = u12[6]; b.y = u12[7];
        up[2] = a; up[3] = b;
    }
    BAR_DATA();

    // u2 = L^T u1  (combined with acc1 += u1*P1)
    u64 u22[8], acc1[8];
    #pragma unroll
    for (int q = 0; q < 8; q++) { u22[q] = 0ull; acc1[q] = 0ull; }
    add_edges(ush, u22);
    #pragma unroll
    for (int q = 0; q < 8; q++) {
        float s0, s1;
        unpack2(u12[q], s0, s1);
        int g0i = 2 * q, g1i = 2 * q + 1;
        {
            u64 a2 = splat2(s0);
            const ulonglong2* mr = (const ulonglong2*)&Mp[g0i][0];
            const ulonglong2* p1 = (const ulonglong2*)&sP1[g0i][0];
            ulonglong2 mA = mr[0], mB = mr[1], mC = mr[2], mD = mr[3];
            ulonglong2 hA = p1[0], hB = p1[1], hC = p1[2], hD = p1[3];
            fma2(u22[0], a2, mA.x); fma2(u22[1], a2, mA.y);
            fma2(u22[2], a2, mB.x); fma2(u22[3], a2, mB.y);
            fma2(u22[4], a2, mC.x); fma2(u22[5], a2, mC.y);
            fma2(u22[6], a2, mD.x); fma2(u22[7], a2, mD.y);
            fma2(acc1[0], a2, hA.x); fma2(acc1[1], a2, hA.y);
            fma2(acc1[2], a2, hB.x); fma2(acc1[3], a2, hB.y);
            fma2(acc1[4], a2, hC.x); fma2(acc1[5], a2, hC.y);
            fma2(acc1[6], a2, hD.x); fma2(acc1[7], a2, hD.y);
        }
        {
            u64 a2 = splat2(s1);
            const ulonglong2* mr = (const ulonglong2*)&Mp[g1i][0];
            const ulonglong2* p1 = (const ulonglong2*)&sP1[g1i][0];
            ulonglong2 mA = mr[0], mB = mr[1], mC = mr[2], mD = mr[3];
            ulonglong2 hA = p1[0], hB = p1[1], hC = p1[2], hD = p1[3];
            fma2(u22[0], a2, mA.x); fma2(u22[1], a2, mA.y);
            fma2(u22[2], a2, mB.x); fma2(u22[3], a2, mB.y);
            fma2(u22[4], a2, mC.x); fma2(u22[5], a2, mC.y);
            fma2(u22[6], a2, mD.x); fma2(u22[7], a2, mD.y);
            fma2(acc1[0], a2, hA.x); fma2(acc1[1], a2, hA.y);
            fma2(acc1[2], a2, hB.x); fma2(acc1[3], a2, hB.y);
            fma2(acc1[4], a2, hC.x); fma2(acc1[5], a2, hC.y);
            fma2(acc1[6], a2, hD.x); fma2(acc1[7], a2, hD.y);
        }
    }

    BAR_ALL();   // #6 join: c ready

    // epilogue: acc0 += c*acc1 + c^2 * (u2 * P2)
    const float c = sc;
    {
        u64 csp = splat2(c);
        #pragma unroll
        for (int q = 0; q < 8; q++) fma2(acc0[q], csp, acc1[q]);
    }
    const float cc = c * c;
    #pragma unroll
    for (int q = 0; q < 8; q++) {
        float s0, s1;
        unpack2(u22[q], s0, s1);
        {
            u64 a2 = splat2(cc * s0);
            const ulonglong2* p2 = (const ulonglong2*)&sP2[2*q][0];
            ulonglong2 hA = p2[0], hB = p2[1], hC = p2[2], hD = p2[3];
            fma2(acc0[0], a2, hA.x); fma2(acc0[1], a2, hA.y);
            fma2(acc0[2], a2, hB.x); fma2(acc0[3], a2, hB.y);
            fma2(acc0[4], a2, hC.x); fma2(acc0[5], a2, hC.y);
            fma2(acc0[6], a2, hD.x); fma2(acc0[7], a2, hD.y);
        }
        {
            u64 a2 = splat2(cc * s1);
            const ulonglong2* p2 = (const ulonglong2*)&sP2[2*q+1][0];
            ulonglong2 hA = p2[0], hB = p2[1], hC = p2[2], hD = p2[3];
            fma2(acc0[0], a2, hA.x); fma2(acc0[1], a2, hA.y);
            fma2(acc0[2], a2, hB.x); fma2(acc0[3], a2, hB.y);
            fma2(acc0[4], a2, hC.x); fma2(acc0[5], a2, hC.y);
            fma2(acc0[6], a2, hD.x); fma2(acc0[7], a2, hD.y);
        }
    }

    ulonglong2* ob = (ulonglong2*)(out + (size_t)blockIdx.x * 2048 + t * 16);
    ulonglong2 s0, s1, s2, s3;
    s0.x = acc0[0]; s0.y = acc0[1];
    s1.x = acc0[2]; s1.y = acc0[3];
    s2.x = acc0[4]; s2.y = acc0[5];
    s3.x = acc0[6]; s3.y = acc0[7];
    ob[0] = s0; ob[1] = s1; ob[2] = s2; ob[3] = s3;
}

extern "C" void kernel_launch(void* const* d_in, const int* in_sizes, int n_in,
                              void* d_out, int out_size) {
    const float* x      = (const float*)d_in[0];  // [1024,128,16]
    const float* weight = (const float*)d_in[1];  // [3,16,16]
    const float* bias   = (const float*)d_in[2];  // [16]
    const float* adj    = (const float*)d_in[3];  // [16,16]
    int batch = in_sizes[0] / (128 * 16);

    sgconv_fused_kernel<<<batch, 160>>>(x, weight, bias, adj, (float*)d_out);
}

// round 15
// speedup vs baseline: 1.0643x; 1.0643x over previous
#include <cuda_runtime.h>
#include <math.h>

typedef unsigned long long u64;

// Exports from setup: lap blocks/edges + combined weights (c folded in).
__device__ __align__(16) float g_Mi[256];   // interior diag block, M[f][g] row-major
__device__ __align__(16) float g_Mb[256];   // boundary diag block (t=0,127)
__device__ __align__(16) float g_eii[16];   // interior temporal coupling
__device__ __align__(16) float g_ebi[16];   // boundary temporal coupling
__device__ __align__(16) float g_G[768];    // G0=W0-W1+W2 ; G1=c(W1-4W2) ; G2=2c^2 W2

__device__ __forceinline__ void fma2(u64& acc, u64 a2, u64 b2) {
    asm("fma.rn.f32x2 %0, %1, %2, %0;" : "+l"(acc) : "l"(a2), "l"(b2));
}
__device__ __forceinline__ u64 splat2(float v) {
    u64 a2;
    asm("mov.b64 %0, {%1, %1};" : "=l"(a2) : "r"(__float_as_uint(v)));
    return a2;
}
__device__ __forceinline__ void unpack2(u64 p, float& lo, float& hi) {
    unsigned l, h;
    asm("mov.b64 {%0, %1}, %2;" : "=r"(l), "=r"(h) : "l"(p));
    lo = __uint_as_float(l); hi = __uint_as_float(h);
}

// ---------------------------------------------------------------------------
// Kernel 1 (R12 verbatim, verified): lap params; sigma_max via modal
// decomposition (max over temporal modes at lam = +/-2cos(pi/129), convexity);
// 16-step Lanczos on explicit B = A^T A + grid Sturm; export blocks + G.
// ---------------------------------------------------------------------------
__global__ void __launch_bounds__(512) setup_kernel(
    const float* __restrict__ adj, const float* __restrict__ weight) {
    __shared__ float sAhat[16][16];
    __shared__ float sMi[16][16], sMb[16][16];
    __shared__ float sA[2][16][16];
    __shared__ float sB[2][16][16];
    __shared__ float seii[16], sebi[16], spb[16], spi[16];
    __shared__ float sc;

    const int tid = threadIdx.x;

    if (tid < 256) {
        int f = tid >> 4, g = tid & 15;
        sAhat[f][g] = (f == g) ? 1.0f : 1.0f / (1.0f + expf(-adj[tid]));
    }
    __syncthreads();

    if (tid < 16) {
        float a = 0.0f;
        #pragma unroll
        for (int g = 0; g < 16; g++) a += sAhat[tid][g];
        spb[tid] = rsqrtf(a + 1.0f);
        spi[tid] = rsqrtf(a + 2.0f);
    }
    __syncthreads();

    if (tid < 256) {
        int f = tid >> 4, g = tid & 15;
        float diag = (f == g) ? 1.0f : 0.0f;
        sMi[f][g] = diag - spi[f] * sAhat[f][g] * spi[g];
        sMb[f][g] = diag - spb[f] * sAhat[f][g] * spb[g];
    }
    if (tid < 16) {
        seii[tid] = -spi[tid] * spi[tid];
        sebi[tid] = -spb[tid] * spi[tid];
    }
    __syncthreads();

    {
        int h = tid >> 8, idx = tid & 255;
        int k = idx >> 4, i = idx & 15;
        float lam = (h ? -2.0f : 2.0f) * cosf(3.14159265358979f / 129.0f);
        sA[h][k][i] = sMi[k][i] + ((k == i) ? lam * seii[k] : 0.0f);
    }
    __syncthreads();

    {
        int h = tid >> 8, idx = tid & 255;
        int i = idx >> 4, j = idx & 15;
        float acc = 0.0f;
        #pragma unroll
        for (int k = 0; k < 16; k++) acc += sA[h][k][i] * sA[h][k][j];
        sB[h][i][j] = acc;
    }
    __syncthreads();

    if (tid < 32) {
        const int lane = tid;
        const int half = lane >> 4;
        const int f    = lane & 15;
        const int base = half << 4;

        float Mr[16];
        #pragma unroll
        for (int g = 0; g < 16; g++) Mr[g] = sB[half][f][g];

        float v, vp = 0.0f;
        {
            unsigned h = (unsigned)(f * 2654435761u) + 0x9E3779B9u;
            h ^= h >> 15; h *= 0x2C1B3C6Du; h ^= h >> 12; h *= 0x297A2D39u; h ^= h >> 15;
            v = (float)(h & 0xFFFFFFu) * (1.0f / 16777216.0f) - 0.5f + 0.03f * (float)f;
            float nn = v * v;
            #pragma unroll
            for (int o = 8; o > 0; o >>= 1) nn += __shfl_xor_sync(0xFFFFFFFFu, nn, o);
            v *= rsqrtf(nn);
        }

        float al[16], be[16];
        float bprev = 0.0f;
        #pragma unroll
        for (int it = 0; it < 16; it++) {
            float w = 0.0f;
            #pragma unroll
            for (int g = 0; g < 16; g++)
                w += Mr[g] * __shfl_sync(0xFFFFFFFFu, v, base + g);
            float pa = v * w;
            #pragma unroll
            for (int o = 8; o > 0; o >>= 1) pa += __shfl_xor_sync(0xFFFFFFFFu, pa, o);
            float alpha = pa;
            w -= alpha * v + bprev * vp;
            float ps = w * w;
            #pragma unroll
            for (int o = 8; o > 0; o >>= 1) ps += __shfl_xor_sync(0xFFFFFFFFu, ps, o);
            float beta = sqrtf(ps);
            al[it] = alpha; be[it] = beta;
            float rb = (beta > 1e-30f) ? 1.0f / beta : 0.0f;
            vp = v; v = w * rb;
            bprev = beta;
        }

        float lo = 0.0f, hi = 8.0f;
        for (int r = 0; r < 6; r++) {
            float x = lo + (hi - lo) * (float)(f + 1) * (1.0f / 17.0f);
            int cnt = 0;
            float d = al[0] - x;
            if (d < 0.0f) cnt++;
            #pragma unroll
            for (int i = 1; i < 16; i++) {
                float dd = (fabsf(d) < 1e-25f) ? ((d < 0.0f) ? -1e-25f : 1e-25f) : d;
                d = (al[i] - x) - (be[i - 1] * be[i - 1]) / dd;
                if (d < 0.0f) cnt++;
            }
            bool ge = (cnt < 16);
            unsigned m = (__ballot_sync(0xFFFFFFFFu, ge) >> (half << 4)) & 0xFFFFu;
            int nge = __popc(m);
            float w17 = (hi - lo) * (1.0f / 17.0f);
            lo = lo + w17 * (float)nge;
            hi = lo + w17;
        }
        float lmax = 0.5f * (lo + hi);
        float other = __shfl_sync(0xFFFFFFFFu, lmax, lane ^ 16);
        lmax = fmaxf(lmax, other);
        if (lane == 0) sc = 2.0f / sqrtf(lmax);
    }
    __syncthreads();

    const float c = sc;
    if (tid < 256) {
        int f = tid >> 4, g = tid & 15;
        g_Mi[tid] = sMi[f][g];
        g_Mb[tid] = sMb[f][g];
        float w0 = weight[tid], w1 = weight[256 + tid], w2 = weight[512 + tid];
        g_G[tid]       = w0 - w1 + w2;
        g_G[256 + tid] = c * (w1 - 4.0f * w2);
        g_G[512 + tid] = 2.0f * c * c * w2;
    }
    if (tid < 16) {
        g_eii[tid] = seii[tid];
        g_ebi[tid] = sebi[tid];
    }
}

// ---------------------------------------------------------------------------
// Kernel 2: merged-accumulator main (R14 data path, acc1 folded into acc0).
// out = bias + x*G0 + u1*G1 + u2*G2;  u1 = L^T x, u2 = L^T u1 (c inside G1,G2).
// Pass 1: u1 + acc += x*G0 (shared splats). Pass 2: u2 + acc += u1*G1.
// Epilogue: acc += u2*G2. Two barriers, single live accumulator set.
// ---------------------------------------------------------------------------
__global__ void __launch_bounds__(128) sgconv_main_kernel(
    const float* __restrict__ x, const float* __restrict__ bias,
    float* __restrict__ out) {
    __shared__ __align__(16) float sMi[16][16], sMb[16][16];
    __shared__ __align__(16) float sG0[16][16], sG1[16][16], sG2[16][16];
    __shared__ __align__(16) float se_i[16], se_b[16];
    __shared__ __align__(16) float sb16[16];
    __shared__ __align__(16) float xsh[128][20];
    __shared__ __align__(16) float ush[128][20];

    const int t = threadIdx.x;
    const bool bnd = (t == 0 || t == 127);

    // param staging (each thread: 2 elements per 256-array)
    {
        ((float*)sMi)[t] = g_Mi[t];        ((float*)sMi)[t + 128] = g_Mi[t + 128];
        ((float*)sMb)[t] = g_Mb[t];        ((float*)sMb)[t + 128] = g_Mb[t + 128];
        ((float*)sG0)[t] = g_G[t];         ((float*)sG0)[t + 128] = g_G[t + 128];
        ((float*)sG1)[t] = g_G[256 + t];   ((float*)sG1)[t + 128] = g_G[384 + t];
        ((float*)sG2)[t] = g_G[512 + t];   ((float*)sG2)[t + 128] = g_G[640 + t];
        if (t < 16) { se_i[t] = g_eii[t]; se_b[t] = g_ebi[t]; sb16[t] = bias[t]; }
    }

    // load x row, publish
    float xw[16];
    {
        const float4* xb = (const float4*)(x + (size_t)blockIdx.x * 2048 + t * 16);
        float4* dst = (float4*)&xsh[t][0];
        #pragma unroll
        for (int q = 0; q < 4; q++) {
            float4 vv = xb[q];
            xw[4*q+0] = vv.x; xw[4*q+1] = vv.y; xw[4*q+2] = vv.z; xw[4*q+3] = vv.w;
            dst[q] = vv;
        }
    }
    __syncthreads();   // barrier 1

    const float (*Mp)[16] = bnd ? sMb : sMi;

    auto add_edges = [&](const float (&nbr)[128][20], u64 (&dst)[8]) {
        if (t > 0) {
            const float* el = (t == 1 || t == 127) ? se_b : se_i;
            const ulonglong2* e2 = (const ulonglong2*)el;
            const ulonglong2* nm = (const ulonglong2*)&nbr[t - 1][0];
            #pragma unroll
            for (int q = 0; q < 4; q++) {
                ulonglong2 ee = e2[q], nn = nm[q];
                fma2(dst[2*q],   ee.x, nn.x);
                fma2(dst[2*q+1], ee.y, nn.y);
            }
        }
        if (t < 127) {
            const float* er = (t == 0 || t == 126) ? se_b : se_i;
            const ulonglong2* e2 = (const ulonglong2*)er;
            const ulonglong2* np = (const ulonglong2*)&nbr[t + 1][0];
            #pragma unroll
            for (int q = 0; q < 4; q++) {
                ulonglong2 ee = e2[q], nn = np[q];
                fma2(dst[2*q],   ee.x, nn.x);
                fma2(dst[2*q+1], ee.y, nn.y);
            }
        }
    };

    // acc = bias
    u64 acc[8];
    {
        const ulonglong2* b2 = (const ulonglong2*)sb16;
        ulonglong2 b01 = b2[0], b23 = b2[1], b45 = b2[2], b67 = b2[3];
        acc[0] = b01.x; acc[1] = b01.y; acc[2] = b23.x; acc[3] = b23.y;
        acc[4] = b45.x; acc[5] = b45.y; acc[6] = b67.x; acc[7] = b67.y;
    }

    // ---- pass 1: u1 = L^T x; acc += x*G0 (shared splats) ----
    u64 u12[8];
    #pragma unroll
    for (int q = 0; q < 8; q++) u12[q] = 0ull;
    add_edges(xsh, u12);
    #pragma unroll
    for (int g = 0; g < 16; g++) {
        u64 a2 = splat2(xw[g]);
        const ulonglong2* mr = (const ulonglong2*)&Mp[g][0];
        const ulonglong2* g0 = (const ulonglong2*)&sG0[g][0];
        ulonglong2 mA = mr[0], mB = mr[1], mC = mr[2], mD = mr[3];
        ulonglong2 hA = g0[0], hB = g0[1], hC = g0[2], hD = g0[3];
        fma2(u12[0], a2, mA.x); fma2(u12[1], a2, mA.y);
        fma2(u12[2], a2, mB.x); fma2(u12[3], a2, mB.y);
        fma2(u12[4], a2, mC.x); fma2(u12[5], a2, mC.y);
        fma2(u12[6], a2, mD.x); fma2(u12[7], a2, mD.y);
        fma2(acc[0], a2, hA.x); fma2(acc[1], a2, hA.y);
        fma2(acc[2], a2, hB.x); fma2(acc[3], a2, hB.y);
        fma2(acc[4], a2, hC.x); fma2(acc[5], a2, hC.y);
        fma2(acc[6], a2, hD.x); fma2(acc[7], a2, hD.y);
    }
    // unpack u1 to floats; publish packed
    float u1w[16];
    #pragma unroll
    for (int q = 0; q < 8; q++) unpack2(u12[q], u1w[2*q], u1w[2*q+1]);
    {
        ulonglong2* up = (ulonglong2*)&ush[t][0];
        ulonglong2 a, b;
        a.x = u12[0]; a.y = u12[1]; b.x = u12[2]; b.y = u12[3];
        up[0] = a; up[1] = b;
        a.x = u12[4]; a.y = u12[5]; b.x = u12[6]; b.y = u12[7];
        up[2] = a; up[3] = b;
    }
    __syncthreads();   // barrier 2

    // ---- pass 2: u2 = L^T u1; acc += u1*G1 (c folded in G1) ----
    u64 u22[8];
    #pragma unroll
    for (int q = 0; q < 8; q++) u22[q] = 0ull;
    add_edges(ush, u22);
    #pragma unroll
    for (int g = 0; g < 16; g++) {
        u64 a2 = splat2(u1w[g]);
        const ulonglong2* mr = (const ulonglong2*)&Mp[g][0];
        const ulonglong2* g1 = (const ulonglong2*)&sG1[g][0];
        ulonglong2 mA = mr[0], mB = mr[1], mC = mr[2], mD = mr[3];
        ulonglong2 hA = g1[0], hB = g1[1], hC = g1[2], hD = g1[3];
        fma2(u22[0], a2, mA.x); fma2(u22[1], a2, mA.y);
        fma2(u22[2], a2, mB.x); fma2(u22[3], a2, mB.y);
        fma2(u22[4], a2, mC.x); fma2(u22[5], a2, mC.y);
        fma2(u22[6], a2, mD.x); fma2(u22[7], a2, mD.y);
        fma2(acc[0], a2, hA.x); fma2(acc[1], a2, hA.y);
        fma2(acc[2], a2, hB.x); fma2(acc[3], a2, hB.y);
        fma2(acc[4], a2, hC.x); fma2(acc[5], a2, hC.y);
        fma2(acc[6], a2, hD.x); fma2(acc[7], a2, hD.y);
    }

    // ---- epilogue: acc += u2*G2 (c^2 folded in G2) ----
    #pragma unroll
    for (int q = 0; q < 8; q++) {
        float s0, s1;
        unpack2(u22[q], s0, s1);
        {
            u64 a2 = splat2(s0);
            const ulonglong2* g2 = (const ulonglong2*)&sG2[2*q][0];
            ulonglong2 hA = g2[0], hB = g2[1], hC = g2[2], hD = g2[3];
            fma2(acc[0], a2, hA.x); fma2(acc[1], a2, hA.y);
            fma2(acc[2], a2, hB.x); fma2(acc[3], a2, hB.y);
            fma2(acc[4], a2, hC.x); fma2(acc[5], a2, hC.y);
            fma2(acc[6], a2, hD.x); fma2(acc[7], a2, hD.y);
        }
        {
            u64 a2 = splat2(s1);
            const ulonglong2* g2 = (const ulonglong2*)&sG2[2*q+1][0];
            ulonglong2 hA = g2[0], hB = g2[1], hC = g2[2], hD = g2[3];
            fma2(acc[0], a2, hA.x); fma2(acc[1], a2, hA.y);
            fma2(acc[2], a2, hB.x); fma2(acc[3], a2, hB.y);
            fma2(acc[4], a2, hC.x); fma2(acc[5], a2, hC.y);
            fma2(acc[6], a2, hD.x); fma2(acc[7], a2, hD.y);
        }
    }

    ulonglong2* ob = (ulonglong2*)(out + (size_t)blockIdx.x * 2048 + t * 16);
    ulonglong2 s0, s1, s2, s3;
    s0.x = acc[0]; s0.y = acc[1];
    s1.x = acc[2]; s1.y = acc[3];
    s2.x = acc[4]; s2.y = acc[5];
    s3.x = acc[6]; s3.y = acc[7];
    ob[0] = s0; ob[1] = s1; ob[2] = s2; ob[3] = s3;
}

extern "C" void kernel_launch(void* const* d_in, const int* in_sizes, int n_in,
                              void* d_out, int out_size) {
    const float* x      = (const float*)d_in[0];  // [1024,128,16]
    const float* weight = (const float*)d_in[1];  // [3,16,16]
    const float* bias   = (const float*)d_in[2];  // [16]
    const float* adj    = (const float*)d_in[3];  // [16,16]
    int batch = in_sizes[0] / (128 * 16);

    setup_kernel<<<1, 512>>>(adj, weight);
    sgconv_main_kernel<<<batch, 128>>>(x, bias, (float*)d_out);
}

// round 16
// speedup vs baseline: 1.2487x; 1.1732x over previous
#include <cuda_runtime.h>
#include <math.h>

typedef unsigned long long u64;

// Exports from setup: lap blocks/edges + combined weights (c folded in).
__device__ __align__(16) float g_Mi[256];   // interior diag block, M[f][g] row-major
__device__ __align__(16) float g_Mb[256];   // boundary diag block (t=0,127)
__device__ __align__(16) float g_eii[16];   // interior temporal coupling
__device__ __align__(16) float g_ebi[16];   // boundary temporal coupling
__device__ __align__(16) float g_G[768];    // G0=W0-W1+W2 ; G1=c(W1-4W2) ; G2=2c^2 W2

__device__ __forceinline__ void fma2(u64& acc, u64 a2, u64 b2) {
    asm("fma.rn.f32x2 %0, %1, %2, %0;" : "+l"(acc) : "l"(a2), "l"(b2));
}
__device__ __forceinline__ u64 splat2(float v) {
    u64 a2;
    asm("mov.b64 %0, {%1, %1};" : "=l"(a2) : "r"(__float_as_uint(v)));
    return a2;
}
__device__ __forceinline__ void unpack2(u64 p, float& lo, float& hi) {
    unsigned l, h;
    asm("mov.b64 {%0, %1}, %2;" : "=r"(l), "=r"(h) : "l"(p));
    lo = __uint_as_float(l); hi = __uint_as_float(h);
}

// ---------------------------------------------------------------------------
// Kernel 1: lap params; sigma_max via modal decomposition (max over temporal
// modes at lam = +/-2cos(pi/129), convexity of the norm in lam — verified
// exact R8-R15). lambda_max(B_h), B_h = A_h^T A_h, via NORMALIZED REPEATED
// SQUARING: S <- S^2/||S^2||_F ten times; lambda = s0 * prod n_k^(1/2^k)
// (log2-accumulated). Fully parallel 512-thread matmuls, no serial chains.
// ---------------------------------------------------------------------------
__global__ void __launch_bounds__(512) setup_kernel(
    const float* __restrict__ adj, const float* __restrict__ weight) {
    __shared__ float sAhat[16][16];
    __shared__ float sMi[16][16], sMb[16][16];
    __shared__ float sS[2][16][16], sT[2][16][16];
    __shared__ float seii[16], sebi[16], spb[16], spi[16];
    __shared__ float sred[16];
    __shared__ float snorm[2], slog[2];
    __shared__ float sc;

    const int tid  = threadIdx.x;
    const int lane = tid & 31;
    const int wrp  = tid >> 5;
    const int h    = tid >> 8;        // half: 0 = +lam, 1 = -lam
    const int idx  = tid & 255;
    const int i    = idx >> 4;
    const int j    = idx & 15;

    if (tid < 256) {
        sAhat[i][j] = (i == j) ? 1.0f : 1.0f / (1.0f + expf(-adj[idx]));
    }
    if (tid == 0) { slog[0] = 0.0f; slog[1] = 0.0f; }
    __syncthreads();

    if (tid < 16) {
        float a = 0.0f;
        #pragma unroll
        for (int g = 0; g < 16; g++) a += sAhat[tid][g];
        spb[tid] = rsqrtf(a + 1.0f);
        spi[tid] = rsqrtf(a + 2.0f);
    }
    __syncthreads();

    if (tid < 256) {
        float diag = (i == j) ? 1.0f : 0.0f;
        sMi[i][j] = diag - spi[i] * sAhat[i][j] * spi[j];
        sMb[i][j] = diag - spb[i] * sAhat[i][j] * spb[j];
    }
    if (tid < 16) {
        seii[tid] = -spi[tid] * spi[tid];
        sebi[tid] = -spb[tid] * spi[tid];
    }
    __syncthreads();

    // A_h = Mi + lam_h diag(eii)  (into sT as scratch)
    {
        float lam = (h ? -2.0f : 2.0f) * cosf(3.14159265358979f / 129.0f);
        sT[h][i][j] = sMi[i][j] + ((i == j) ? lam * seii[i] : 0.0f);
    }
    __syncthreads();

    // B_h = A_h^T A_h ; Frobenius norm (s0) ; normalize into sS
    float b = 0.0f;
    {
        #pragma unroll
        for (int k = 0; k < 16; k++) b += sT[h][k][i] * sT[h][k][j];
    }
    {
        float p = b * b;
        #pragma unroll
        for (int o = 16; o > 0; o >>= 1) p += __shfl_xor_sync(0xFFFFFFFFu, p, o);
        if (lane == 0) sred[wrp] = p;
    }
    __syncthreads();
    if (idx == 0) {   // one leader per half
        float n2 = 0.0f;
        #pragma unroll
        for (int w = 0; w < 8; w++) n2 += sred[h * 8 + w];
        float n = sqrtf(n2);
        snorm[h] = 1.0f / n;
        slog[h] += log2f(n);     // weight 2^0 (this is s0)
    }
    __syncthreads();
    sS[h][i][j] = b * snorm[h];
    __syncthreads();

    // 10 rounds of normalized squaring
    for (int k = 1; k <= 10; k++) {
        float tt = 0.0f;
        #pragma unroll
        for (int m = 0; m < 16; m++) tt += sS[h][i][m] * sS[h][m][j];
        float p = tt * tt;
        #pragma unroll
        for (int o = 16; o > 0; o >>= 1) p += __shfl_xor_sync(0xFFFFFFFFu, p, o);
        if (lane == 0) sred[wrp] = p;
        __syncthreads();                       // sS reads + sred writes done
        if (idx == 0) {
            float n2 = 0.0f;
            #pragma unroll
            for (int w = 0; w < 8; w++) n2 += sred[h * 8 + w];
            float n = sqrtf(n2);
            snorm[h] = 1.0f / n;
            slog[h] += log2f(n) * exp2f(-(float)k);
        }
        __syncthreads();                       // snorm ready
        sS[h][i][j] = tt * snorm[h];
        __syncthreads();                       // new sS ready
    }

    if (tid == 0) {
        float l0 = exp2f(slog[0]);             // lambda_max(B_0) = sigma^2
        float l1 = exp2f(slog[1]);
        sc = 2.0f / sqrtf(fmaxf(l0, l1));
    }
    __syncthreads();

    // exports (same as verified R12)
    const float c = sc;
    if (tid < 256) {
        g_Mi[idx] = sMi[i][j];
        g_Mb[idx] = sMb[i][j];
        float w0 = weight[idx], w1 = weight[256 + idx], w2 = weight[512 + idx];
        g_G[idx]       = w0 - w1 + w2;
        g_G[256 + idx] = c * (w1 - 4.0f * w2);
        g_G[512 + idx] = 2.0f * c * c * w2;
    }
    if (tid < 16) {
        g_eii[tid] = seii[tid];
        g_ebi[tid] = sebi[tid];
    }
}

// ---------------------------------------------------------------------------
// Kernel 2: merged-accumulator main (R15 data path, verified), with a raised
// register budget (launch_bounds(128,4) -> up to 128 regs) so ptxas can
// pipeline the uniform LDS rows deeper. Same achieved occupancy (4 blocks/SM).
// out = bias + x*G0 + u1*G1 + u2*G2;  u1 = L^T x, u2 = L^T u1.
// ---------------------------------------------------------------------------
__global__ void __launch_bounds__(128, 4) sgconv_main_kernel(
    const float* __restrict__ x, const float* __restrict__ bias,
    float* __restrict__ out) {
    __shared__ __align__(16) float sMi[16][16], sMb[16][16];
    __shared__ __align__(16) float sG0[16][16], sG1[16][16], sG2[16][16];
    __shared__ __align__(16) float se_i[16], se_b[16];
    __shared__ __align__(16) float sb16[16];
    __shared__ __align__(16) float xsh[128][20];
    __shared__ __align__(16) float ush[128][20];

    const int t = threadIdx.x;
    const bool bnd = (t == 0 || t == 127);

    {
        ((float*)sMi)[t] = g_Mi[t];        ((float*)sMi)[t + 128] = g_Mi[t + 128];
        ((float*)sMb)[t] = g_Mb[t];        ((float*)sMb)[t + 128] = g_Mb[t + 128];
        ((float*)sG0)[t] = g_G[t];         ((float*)sG0)[t + 128] = g_G[t + 128];
        ((float*)sG1)[t] = g_G[256 + t];   ((float*)sG1)[t + 128] = g_G[384 + t];
        ((float*)sG2)[t] = g_G[512 + t];   ((float*)sG2)[t + 128] = g_G[640 + t];
        if (t < 16) { se_i[t] = g_eii[t]; se_b[t] = g_ebi[t]; sb16[t] = bias[t]; }
    }

    float xw[16];
    {
        const float4* xb = (const float4*)(x + (size_t)blockIdx.x * 2048 + t * 16);
        float4* dst = (float4*)&xsh[t][0];
        #pragma unroll
        for (int q = 0; q < 4; q++) {
            float4 vv = xb[q];
            xw[4*q+0] = vv.x; xw[4*q+1] = vv.y; xw[4*q+2] = vv.z; xw[4*q+3] = vv.w;
            dst[q] = vv;
        }
    }
    __syncthreads();   // barrier 1

    const float (*Mp)[16] = bnd ? sMb : sMi;

    auto add_edges = [&](const float (&nbr)[128][20], u64 (&dst)[8]) {
        if (t > 0) {
            const float* el = (t == 1 || t == 127) ? se_b : se_i;
            const ulonglong2* e2 = (const ulonglong2*)el;
            const ulonglong2* nm = (const ulonglong2*)&nbr[t - 1][0];
            #pragma unroll
            for (int q = 0; q < 4; q++) {
                ulonglong2 ee = e2[q], nn = nm[q];
                fma2(dst[2*q],   ee.x, nn.x);
                fma2(dst[2*q+1], ee.y, nn.y);
            }
        }
        if (t < 127) {
            const float* er = (t == 0 || t == 126) ? se_b : se_i;
            const ulonglong2* e2 = (const ulonglong2*)er;
            const ulonglong2* np = (const ulonglong2*)&nbr[t + 1][0];
            #pragma unroll
            for (int q = 0; q < 4; q++) {
                ulonglong2 ee = e2[q], nn = np[q];
                fma2(dst[2*q],   ee.x, nn.x);
                fma2(dst[2*q+1], ee.y, nn.y);
            }
        }
    };

    u64 acc[8];
    {
        const ulonglong2* b2 = (const ulonglong2*)sb16;
        ulonglong2 b01 = b2[0], b23 = b2[1], b45 = b2[2], b67 = b2[3];
        acc[0] = b01.x; acc[1] = b01.y; acc[2] = b23.x; acc[3] = b23.y;
        acc[4] = b45.x; acc[5] = b45.y; acc[6] = b67.x; acc[7] = b67.y;
    }

    // pass 1: u1 = L^T x; acc += x*G0
    u64 u12[8];
    #pragma unroll
    for (int q = 0; q < 8; q++) u12[q] = 0ull;
    add_edges(xsh, u12);
    #pragma unroll
    for (int g = 0; g < 16; g++) {
        u64 a2 = splat2(xw[g]);
        const ulonglong2* mr = (const ulonglong2*)&Mp[g][0];
        const ulonglong2* g0 = (const ulonglong2*)&sG0[g][0];
        ulonglong2 mA = mr[0], mB = mr[1], mC = mr[2], mD = mr[3];
        ulonglong2 hA = g0[0], hB = g0[1], hC = g0[2], hD = g0[3];
        fma2(u12[0], a2, mA.x); fma2(u12[1], a2, mA.y);
        fma2(u12[2], a2, mB.x); fma2(u12[3], a2, mB.y);
        fma2(u12[4], a2, mC.x); fma2(u12[5], a2, mC.y);
        fma2(u12[6], a2, mD.x); fma2(u12[7], a2, mD.y);
        fma2(acc[0], a2, hA.x); fma2(acc[1], a2, hA.y);
        fma2(acc[2], a2, hB.x); fma2(acc[3], a2, hB.y);
        fma2(acc[4], a2, hC.x); fma2(acc[5], a2, hC.y);
        fma2(acc[6], a2, hD.x); fma2(acc[7], a2, hD.y);
    }
    float u1w[16];
    #pragma unroll
    for (int q = 0; q < 8; q++) unpack2(u12[q], u1w[2*q], u1w[2*q+1]);
    {
        ulonglong2* up = (ulonglong2*)&ush[t][0];
        ulonglong2 a, b;
        a.x = u12[0]; a.y = u12[1]; b.x = u12[2]; b.y = u12[3];
        up[0] = a; up[1] = b;
        a.x = u12[4]; a.y = u12[5]; b.x = u12[6]; b.y = u12[7];
        up[2] = a; up[3] = b;
    }
    __syncthreads();   // barrier 2

    // pass 2: u2 = L^T u1; acc += u1*G1
    u64 u22[8];
    #pragma unroll
    for (int q = 0; q < 8; q++) u22[q] = 0ull;
    add_edges(ush, u22);
    #pragma unroll
    for (int g = 0; g < 16; g++) {
        u64 a2 = splat2(u1w[g]);
        const ulonglong2* mr = (const ulonglong2*)&Mp[g][0];
        const ulonglong2* g1 = (const ulonglong2*)&sG1[g][0];
        ulonglong2 mA = mr[0], mB = mr[1], mC = mr[2], mD = mr[3];
        ulonglong2 hA = g1[0], hB = g1[1], hC = g1[2], hD = g1[3];
        fma2(u22[0], a2, mA.x); fma2(u22[1], a2, mA.y);
        fma2(u22[2], a2, mB.x); fma2(u22[3], a2, mB.y);
        fma2(u22[4], a2, mC.x); fma2(u22[5], a2, mC.y);
        fma2(u22[6], a2, mD.x); fma2(u22[7], a2, mD.y);
        fma2(acc[0], a2, hA.x); fma2(acc[1], a2, hA.y);
        fma2(acc[2], a2, hB.x); fma2(acc[3], a2, hB.y);
        fma2(acc[4], a2, hC.x); fma2(acc[5], a2, hC.y);
        fma2(acc[6], a2, hD.x); fma2(acc[7], a2, hD.y);
    }

    // epilogue: acc += u2*G2
    #pragma unroll
    for (int q = 0; q < 8; q++) {
        float s0, s1;
        unpack2(u22[q], s0, s1);
        {
            u64 a2 = splat2(s0);
            const ulonglong2* g2 = (const ulonglong2*)&sG2[2*q][0];
            ulonglong2 hA = g2[0], hB = g2[1], hC = g2[2], hD = g2[3];
            fma2(acc[0], a2, hA.x); fma2(acc[1], a2, hA.y);
            fma2(acc[2], a2, hB.x); fma2(acc[3], a2, hB.y);
            fma2(acc[4], a2, hC.x); fma2(acc[5], a2, hC.y);
            fma2(acc[6], a2, hD.x); fma2(acc[7], a2, hD.y);
        }
        {
            u64 a2 = splat2(s1);
            const ulonglong2* g2 = (const ulonglong2*)&sG2[2*q+1][0];
            ulonglong2 hA = g2[0], hB = g2[1], hC = g2[2], hD = g2[3];
            fma2(acc[0], a2, hA.x); fma2(acc[1], a2, hA.y);
            fma2(acc[2], a2, hB.x); fma2(acc[3], a2, hB.y);
            fma2(acc[4], a2, hC.x); fma2(acc[5], a2, hC.y);
            fma2(acc[6], a2, hD.x); fma2(acc[7], a2, hD.y);
        }
    }

    ulonglong2* ob = (ulonglong2*)(out + (size_t)blockIdx.x * 2048 + t * 16);
    ulonglong2 s0, s1, s2, s3;
    s0.x = acc[0]; s0.y = acc[1];
    s1.x = acc[2]; s1.y = acc[3];
    s2.x = acc[4]; s2.y = acc[5];
    s3.x = acc[6]; s3.y = acc[7];
    ob[0] = s0; ob[1] = s1; ob[2] = s2; ob[3] = s3;
}

extern "C" void kernel_launch(void* const* d_in, const int* in_sizes, int n_in,
                              void* d_out, int out_size) {
    const float* x      = (const float*)d_in[0];  // [1024,128,16]
    const float* weight = (const float*)d_in[1];  // [3,16,16]
    const float* bias   = (const float*)d_in[2];  // [16]
    const float* adj    = (const float*)d_in[3];  // [16,16]
    int batch = in_sizes[0] / (128 * 16);

    setup_kernel<<<1, 512>>>(adj, weight);
    sgconv_main_kernel<<<batch, 128>>>(x, bias, (float*)d_out);
}

// round 17
// speedup vs baseline: 1.3872x; 1.1110x over previous
#include <cuda_runtime.h>
#include <math.h>

typedef unsigned long long u64;

// Exports from setup: lap blocks/edges + combined weights (c folded in).
__device__ __align__(16) float g_Mi[256];   // interior diag block, M[f][g] row-major
__device__ __align__(16) float g_Mb[256];   // boundary diag block (t=0,127)
__device__ __align__(16) float g_eii[16];   // interior temporal coupling
__device__ __align__(16) float g_ebi[16];   // boundary temporal coupling
__device__ __align__(16) float g_G[768];    // G0=W0-W1+W2 ; G1=c(W1-4W2) ; G2=2c^2 W2

__device__ __forceinline__ void fma2(u64& acc, u64 a2, u64 b2) {
    asm("fma.rn.f32x2 %0, %1, %2, %0;" : "+l"(acc) : "l"(a2), "l"(b2));
}
__device__ __forceinline__ u64 splat2(float v) {
    u64 a2;
    asm("mov.b64 %0, {%1, %1};" : "=l"(a2) : "r"(__float_as_uint(v)));
    return a2;
}
__device__ __forceinline__ void unpack2(u64 p, float& lo, float& hi) {
    unsigned l, h;
    asm("mov.b64 {%0, %1}, %2;" : "=r"(l), "=r"(h) : "l"(p));
    lo = __uint_as_float(l); hi = __uint_as_float(h);
}

// ---------------------------------------------------------------------------
// Kernel 1 (R16 verbatim, verified): lap params; sigma_max via modal
// decomposition (max at lam = +/-2cos(pi/129)); lambda_max by normalized
// repeated squaring (10 rounds), fully parallel; export blocks + G.
// ---------------------------------------------------------------------------
__global__ void __launch_bounds__(512) setup_kernel(
    const float* __restrict__ adj, const float* __restrict__ weight) {
    __shared__ float sAhat[16][16];
    __shared__ float sMi[16][16], sMb[16][16];
    __shared__ float sS[2][16][16], sT[2][16][16];
    __shared__ float seii[16], sebi[16], spb[16], spi[16];
    __shared__ float sred[16];
    __shared__ float snorm[2], slog[2];
    __shared__ float sc;

    const int tid  = threadIdx.x;
    const int lane = tid & 31;
    const int wrp  = tid >> 5;
    const int h    = tid >> 8;
    const int idx  = tid & 255;
    const int i    = idx >> 4;
    const int j    = idx & 15;

    if (tid < 256) {
        sAhat[i][j] = (i == j) ? 1.0f : 1.0f / (1.0f + expf(-adj[idx]));
    }
    if (tid == 0) { slog[0] = 0.0f; slog[1] = 0.0f; }
    __syncthreads();

    if (tid < 16) {
        float a = 0.0f;
        #pragma unroll
        for (int g = 0; g < 16; g++) a += sAhat[tid][g];
        spb[tid] = rsqrtf(a + 1.0f);
        spi[tid] = rsqrtf(a + 2.0f);
    }
    __syncthreads();

    if (tid < 256) {
        float diag = (i == j) ? 1.0f : 0.0f;
        sMi[i][j] = diag - spi[i] * sAhat[i][j] * spi[j];
        sMb[i][j] = diag - spb[i] * sAhat[i][j] * spb[j];
    }
    if (tid < 16) {
        seii[tid] = -spi[tid] * spi[tid];
        sebi[tid] = -spb[tid] * spi[tid];
    }
    __syncthreads();

    {
        float lam = (h ? -2.0f : 2.0f) * cosf(3.14159265358979f / 129.0f);
        sT[h][i][j] = sMi[i][j] + ((i == j) ? lam * seii[i] : 0.0f);
    }
    __syncthreads();

    float b = 0.0f;
    {
        #pragma unroll
        for (int k = 0; k < 16; k++) b += sT[h][k][i] * sT[h][k][j];
    }
    {
        float p = b * b;
        #pragma unroll
        for (int o = 16; o > 0; o >>= 1) p += __shfl_xor_sync(0xFFFFFFFFu, p, o);
        if (lane == 0) sred[wrp] = p;
    }
    __syncthreads();
    if (idx == 0) {
        float n2 = 0.0f;
        #pragma unroll
        for (int w = 0; w < 8; w++) n2 += sred[h * 8 + w];
        float n = sqrtf(n2);
        snorm[h] = 1.0f / n;
        slog[h] += log2f(n);
    }
    __syncthreads();
    sS[h][i][j] = b * snorm[h];
    __syncthreads();

    for (int k = 1; k <= 10; k++) {
        float tt = 0.0f;
        #pragma unroll
        for (int m = 0; m < 16; m++) tt += sS[h][i][m] * sS[h][m][j];
        float p = tt * tt;
        #pragma unroll
        for (int o = 16; o > 0; o >>= 1) p += __shfl_xor_sync(0xFFFFFFFFu, p, o);
        if (lane == 0) sred[wrp] = p;
        __syncthreads();
        if (idx == 0) {
            float n2 = 0.0f;
            #pragma unroll
            for (int w = 0; w < 8; w++) n2 += sred[h * 8 + w];
            float n = sqrtf(n2);
            snorm[h] = 1.0f / n;
            slog[h] += log2f(n) * exp2f(-(float)k);
        }
        __syncthreads();
        sS[h][i][j] = tt * snorm[h];
        __syncthreads();
    }

    if (tid == 0) {
        float l0 = exp2f(slog[0]);
        float l1 = exp2f(slog[1]);
        sc = 2.0f / sqrtf(fmaxf(l0, l1));
    }
    __syncthreads();

    const float c = sc;
    if (tid < 256) {
        g_Mi[idx] = sMi[i][j];
        g_Mb[idx] = sMb[i][j];
        float w0 = weight[idx], w1 = weight[256 + idx], w2 = weight[512 + idx];
        g_G[idx]       = w0 - w1 + w2;
        g_G[256 + idx] = c * (w1 - 4.0f * w2);
        g_G[512 + idx] = 2.0f * c * c * w2;
    }
    if (tid < 16) {
        g_eii[tid] = seii[tid];
        g_ebi[tid] = sebi[tid];
    }
}

// ---------------------------------------------------------------------------
// Kernel 2: TWO batch rows per thread. Each uniform matrix-row LDS feeds two
// splat-FMA pairs (LDS per unit work halved; LDS was the binding resource at
// L1=72.6%). vsh tile reused for u1 (extra barrier). Grid = batch/2.
// out = bias + x*G0 + u1*G1 + u2*G2;  u1 = L^T x, u2 = L^T u1.
// ---------------------------------------------------------------------------
__global__ void __launch_bounds__(128, 4) sgconv_main_kernel(
    const float* __restrict__ x, const float* __restrict__ bias,
    float* __restrict__ out) {
    __shared__ __align__(16) float sMi[16][16], sMb[16][16];
    __shared__ __align__(16) float sG0[16][16], sG1[16][16], sG2[16][16];
    __shared__ __align__(16) float se_i[16], se_b[16];
    __shared__ __align__(16) float sb16[16];
    __shared__ __align__(16) float vsh[2][128][20];   // x tile, then u1 tile

    const int t = threadIdx.x;
    const bool bnd = (t == 0 || t == 127);
    const size_t base0 = (size_t)blockIdx.x * 4096 + t * 16;   // batch row 2b
    const size_t base1 = base0 + 2048;                          // batch row 2b+1

    {
        ((float*)sMi)[t] = g_Mi[t];        ((float*)sMi)[t + 128] = g_Mi[t + 128];
        ((float*)sMb)[t] = g_Mb[t];        ((float*)sMb)[t + 128] = g_Mb[t + 128];
        ((float*)sG0)[t] = g_G[t];         ((float*)sG0)[t + 128] = g_G[t + 128];
        ((float*)sG1)[t] = g_G[256 + t];   ((float*)sG1)[t + 128] = g_G[384 + t];
        ((float*)sG2)[t] = g_G[512 + t];   ((float*)sG2)[t + 128] = g_G[640 + t];
        if (t < 16) { se_i[t] = g_eii[t]; se_b[t] = g_ebi[t]; sb16[t] = bias[t]; }
    }

    float xw0[16], xw1[16];
    {
        const float4* xb0 = (const float4*)(x + base0);
        const float4* xb1 = (const float4*)(x + base1);
        float4* d0 = (float4*)&vsh[0][t][0];
        float4* d1 = (float4*)&vsh[1][t][0];
        #pragma unroll
        for (int q = 0; q < 4; q++) {
            float4 v0 = xb0[q], v1 = xb1[q];
            xw0[4*q+0] = v0.x; xw0[4*q+1] = v0.y; xw0[4*q+2] = v0.z; xw0[4*q+3] = v0.w;
            xw1[4*q+0] = v1.x; xw1[4*q+1] = v1.y; xw1[4*q+2] = v1.z; xw1[4*q+3] = v1.w;
            d0[q] = v0; d1[q] = v1;
        }
    }
    __syncthreads();   // barrier 1: params + x tiles

    const float (*Mp)[16] = bnd ? sMb : sMi;

    auto add_edges = [&](const float (&nbr)[128][20], u64 (&dst)[8]) {
        if (t > 0) {
            const float* el = (t == 1 || t == 127) ? se_b : se_i;
            const ulonglong2* e2 = (const ulonglong2*)el;
            const ulonglong2* nm = (const ulonglong2*)&nbr[t - 1][0];
            #pragma unroll
            for (int q = 0; q < 4; q++) {
                ulonglong2 ee = e2[q], nn = nm[q];
                fma2(dst[2*q],   ee.x, nn.x);
                fma2(dst[2*q+1], ee.y, nn.y);
            }
        }
        if (t < 127) {
            const float* er = (t == 0 || t == 126) ? se_b : se_i;
            const ulonglong2* e2 = (const ulonglong2*)er;
            const ulonglong2* np = (const ulonglong2*)&nbr[t + 1][0];
            #pragma unroll
            for (int q = 0; q < 4; q++) {
                ulonglong2 ee = e2[q], nn = np[q];
                fma2(dst[2*q],   ee.x, nn.x);
                fma2(dst[2*q+1], ee.y, nn.y);
            }
        }
    };

    // acc = bias (both rows)
    u64 acc0[8], acc1[8];
    {
        const ulonglong2* b2 = (const ulonglong2*)sb16;
        ulonglong2 b01 = b2[0], b23 = b2[1], b45 = b2[2], b67 = b2[3];
        acc0[0] = b01.x; acc0[1] = b01.y; acc0[2] = b23.x; acc0[3] = b23.y;
        acc0[4] = b45.x; acc0[5] = b45.y; acc0[6] = b67.x; acc0[7] = b67.y;
        #pragma unroll
        for (int q = 0; q < 8; q++) acc1[q] = acc0[q];
    }

    // ---- pass 1: u1 = L^T x; acc += x*G0 (matrix rows shared by both rows) ----
    u64 p0[8], p1[8];
    #pragma unroll
    for (int q = 0; q < 8; q++) { p0[q] = 0ull; p1[q] = 0ull; }
    add_edges(vsh[0], p0);
    add_edges(vsh[1], p1);
    #pragma unroll
    for (int g = 0; g < 16; g++) {
        const ulonglong2* mr = (const ulonglong2*)&Mp[g][0];
        const ulonglong2* g0 = (const ulonglong2*)&sG0[g][0];
        ulonglong2 mA = mr[0], mB = mr[1], mC = mr[2], mD = mr[3];
        ulonglong2 hA = g0[0], hB = g0[1], hC = g0[2], hD = g0[3];
        u64 a0 = splat2(xw0[g]);
        u64 a1 = splat2(xw1[g]);
        fma2(p0[0], a0, mA.x); fma2(p0[1], a0, mA.y);
        fma2(p0[2], a0, mB.x); fma2(p0[3], a0, mB.y);
        fma2(p0[4], a0, mC.x); fma2(p0[5], a0, mC.y);
        fma2(p0[6], a0, mD.x); fma2(p0[7], a0, mD.y);
        fma2(p1[0], a1, mA.x); fma2(p1[1], a1, mA.y);
        fma2(p1[2], a1, mB.x); fma2(p1[3], a1, mB.y);
        fma2(p1[4], a1, mC.x); fma2(p1[5], a1, mC.y);
        fma2(p1[6], a1, mD.x); fma2(p1[7], a1, mD.y);
        fma2(acc0[0], a0, hA.x); fma2(acc0[1], a0, hA.y);
        fma2(acc0[2], a0, hB.x); fma2(acc0[3], a0, hB.y);
        fma2(acc0[4], a0, hC.x); fma2(acc0[5], a0, hC.y);
        fma2(acc0[6], a0, hD.x); fma2(acc0[7], a0, hD.y);
        fma2(acc1[0], a1, hA.x); fma2(acc1[1], a1, hA.y);
        fma2(acc1[2], a1, hB.x); fma2(acc1[3], a1, hB.y);
        fma2(acc1[4], a1, hC.x); fma2(acc1[5], a1, hC.y);
        fma2(acc1[6], a1, hD.x); fma2(acc1[7], a1, hD.y);
    }
    // u1 floats into xw (reuse), publish u1 into vsh after a barrier
    #pragma unroll
    for (int q = 0; q < 8; q++) {
        unpack2(p0[q], xw0[2*q], xw0[2*q+1]);
        unpack2(p1[q], xw1[2*q], xw1[2*q+1]);
    }
    __syncthreads();   // barrier 2: everyone done reading x tiles
    {
        ulonglong2* u0 = (ulonglong2*)&vsh[0][t][0];
        ulonglong2* u1 = (ulonglong2*)&vsh[1][t][0];
        ulonglong2 a, b;
        a.x = p0[0]; a.y = p0[1]; b.x = p0[2]; b.y = p0[3];
        u0[0] = a; u0[1] = b;
        a.x = p0[4]; a.y = p0[5]; b.x = p0[6]; b.y = p0[7];
        u0[2] = a; u0[3] = b;
        a.x = p1[0]; a.y = p1[1]; b.x = p1[2]; b.y = p1[3];
        u1[0] = a; u1[1] = b;
        a.x = p1[4]; a.y = p1[5]; b.x = p1[6]; b.y = p1[7];
        u1[2] = a; u1[3] = b;
    }
    __syncthreads();   // barrier 3: u1 tiles ready

    // ---- pass 2: u2 = L^T u1; acc += u1*G1 ----
    #pragma unroll
    for (int q = 0; q < 8; q++) { p0[q] = 0ull; p1[q] = 0ull; }
    add_edges(vsh[0], p0);
    add_edges(vsh[1], p1);
    #pragma unroll
    for (int g = 0; g < 16; g++) {
        const ulonglong2* mr = (const ulonglong2*)&Mp[g][0];
        const ulonglong2* g1 = (const ulonglong2*)&sG1[g][0];
        ulonglong2 mA = mr[0], mB = mr[1], mC = mr[2], mD = mr[3];
        ulonglong2 hA = g1[0], hB = g1[1], hC = g1[2], hD = g1[3];
        u64 a0 = splat2(xw0[g]);
        u64 a1 = splat2(xw1[g]);
        fma2(p0[0], a0, mA.x); fma2(p0[1], a0, mA.y);
        fma2(p0[2], a0, mB.x); fma2(p0[3], a0, mB.y);
        fma2(p0[4], a0, mC.x); fma2(p0[5], a0, mC.y);
        fma2(p0[6], a0, mD.x); fma2(p0[7], a0, mD.y);
        fma2(p1[0], a1, mA.x); fma2(p1[1], a1, mA.y);
        fma2(p1[2], a1, mB.x); fma2(p1[3], a1, mB.y);
        fma2(p1[4], a1, mC.x); fma2(p1[5], a1, mC.y);
        fma2(p1[6], a1, mD.x); fma2(p1[7], a1, mD.y);
        fma2(acc0[0], a0, hA.x); fma2(acc0[1], a0, hA.y);
        fma2(acc0[2], a0, hB.x); fma2(acc0[3], a0, hB.y);
        fma2(acc0[4], a0, hC.x); fma2(acc0[5], a0, hC.y);
        fma2(acc0[6], a0, hD.x); fma2(acc0[7], a0, hD.y);
        fma2(acc1[0], a1, hA.x); fma2(acc1[1], a1, hA.y);
        fma2(acc1[2], a1, hB.x); fma2(acc1[3], a1, hB.y);
        fma2(acc1[4], a1, hC.x); fma2(acc1[5], a1, hC.y);
        fma2(acc1[6], a1, hD.x); fma2(acc1[7], a1, hD.y);
    }

    // ---- epilogue: acc += u2*G2 ----
    #pragma unroll
    for (int q = 0; q < 8; q++) {
        float s00, s01, s10, s11;
        unpack2(p0[q], s00, s01);
        unpack2(p1[q], s10, s11);
        {
            const ulonglong2* g2 = (const ulonglong2*)&sG2[2*q][0];
            ulonglong2 hA = g2[0], hB = g2[1], hC = g2[2], hD = g2[3];
            u64 a0 = splat2(s00), a1 = splat2(s10);
            fma2(acc0[0], a0, hA.x); fma2(acc0[1], a0, hA.y);
            fma2(acc0[2], a0, hB.x); fma2(acc0[3], a0, hB.y);
            fma2(acc0[4], a0, hC.x); fma2(acc0[5], a0, hC.y);
            fma2(acc0[6], a0, hD.x); fma2(acc0[7], a0, hD.y);
            fma2(acc1[0], a1, hA.x); fma2(acc1[1], a1, hA.y);
            fma2(acc1[2], a1, hB.x); fma2(acc1[3], a1, hB.y);
            fma2(acc1[4], a1, hC.x); fma2(acc1[5], a1, hC.y);
            fma2(acc1[6], a1, hD.x); fma2(acc1[7], a1, hD.y);
        }
        {
            const ulonglong2* g2 = (const ulonglong2*)&sG2[2*q+1][0];
            ulonglong2 hA = g2[0], hB = g2[1], hC = g2[2], hD = g2[3];
            u64 a0 = splat2(s01), a1 = splat2(s11);
            fma2(acc0[0], a0, hA.x); fma2(acc0[1], a0, hA.y);
            fma2(acc0[2], a0, hB.x); fma2(acc0[3], a0, hB.y);
            fma2(acc0[4], a0, hC.x); fma2(acc0[5], a0, hC.y);
            fma2(acc0[6], a0, hD.x); fma2(acc0[7], a0, hD.y);
            fma2(acc1[0], a1, hA.x); fma2(acc1[1], a1, hA.y);
            fma2(acc1[2], a1, hB.x); fma2(acc1[3], a1, hB.y);
            fma2(acc1[4], a1, hC.x); fma2(acc1[5], a1, hC.y);
            fma2(acc1[6], a1, hD.x); fma2(acc1[7], a1, hD.y);
        }
    }

    {
        ulonglong2* ob0 = (ulonglong2*)(out + base0);
        ulonglong2* ob1 = (ulonglong2*)(out + base1);
        ulonglong2 s;
        s.x = acc0[0]; s.y = acc0[1]; ob0[0] = s;
        s.x = acc0[2]; s.y = acc0[3]; ob0[1] = s;
        s.x = acc0[4]; s.y = acc0[5]; ob0[2] = s;
        s.x = acc0[6]; s.y = acc0[7]; ob0[3] = s;
        s.x = acc1[0]; s.y = acc1[1]; ob1[0] = s;
        s.x = acc1[2]; s.y = acc1[3]; ob1[1] = s;
        s.x = acc1[4]; s.y = acc1[5]; ob1[2] = s;
        s.x = acc1[6]; s.y = acc1[7]; ob1[3] = s;
    }
}

extern "C" void kernel_launch(void* const* d_in, const int* in_sizes, int n_in,
                              void* d_out, int out_size) {
    const float* x      = (const float*)d_in[0];  // [1024,128,16]
    const float* weight = (const float*)d_in[1];  // [3,16,16]
    const float* bias   = (const float*)d_in[2];  // [16]
    const float* adj    = (const float*)d_in[3];  // [16,16]
    int batch = in_sizes[0] / (128 * 16);

    setup_kernel<<<1, 512>>>(adj, weight);
    sgconv_main_kernel<<<batch / 2, 128>>>(x, bias, (float*)d_out);
}